// round 17
// baseline (speedup 1.0000x reference)
#include <cuda_runtime.h>
#include <cstdint>

#define NS   4
#define NB   2
#define NF   64
#define NP   16
#define THW  131072                 // 2^17
#define NPIX (NB * THW)             // 262144
#define OUT_ELEMS (NB * NF * THW)   // 16777216 floats; alpha follows

typedef unsigned long long u64;

__device__ __forceinline__ u64 pack2(float lo, float hi) {
    u64 r;
    asm("mov.b64 %0, {%1, %2};" : "=l"(r) : "f"(lo), "f"(hi));
    return r;
}
__device__ __forceinline__ void unpack2(u64 v, float& lo, float& hi) {
    asm("mov.b64 {%0, %1}, %2;" : "=f"(lo), "=f"(hi) : "l"(v));
}
__device__ __forceinline__ u64 fma2(u64 a, u64 b, u64 c) {
    u64 d;
    asm("fma.rn.f32x2 %0, %1, %2, %3;" : "=l"(d) : "l"(a), "l"(b), "l"(c));
    return d;
}
__device__ __forceinline__ u64 mul2(u64 a, u64 b) {
    u64 d;
    asm("mul.rn.f32x2 %0, %1, %2;" : "=l"(d) : "l"(a), "l"(b));
    return d;
}

__global__ __launch_bounds__(128, 4) void gssm_kernel(
    const float* __restrict__ feats,   // (S,B,F,T,H,W)
    const float* __restrict__ ps,      // (B,P,T,H,W)
    const float* __restrict__ w1,      // (HID, F+P)
    const float* __restrict__ gamma,
    const float* __restrict__ beta,
    const float* __restrict__ mean,
    const float* __restrict__ var,
    const float* __restrict__ w2,      // (HID,)
    float* __restrict__ out)           // [OUT_ELEMS out][B*S*THW alpha]
{
    __shared__ u64 w1t2[80][32];       // {w,w} packed, PLAIN o layout (consecutive)
    __shared__ u64 sc2[32], sh2[32];
    __shared__ float w2s[32];

    const int tid = threadIdx.x;

    // ---- stage weights / BN ----
    for (int idx = tid; idx < 80 * 32; idx += 128) {
        int k = idx >> 5, o = idx & 31;
        float w = w1[o * 80 + k];
        w1t2[k][o] = pack2(w, w);
    }
    if (tid < 32) {
        int o = tid;
        float s  = gamma[o] / sqrtf(var[o] + 1e-5f);
        float sh = beta[o] - mean[o] * s;
        sc2[o] = pack2(s, s);
        sh2[o] = pack2(sh, sh);
        w2s[o] = w2[o];
    }
    __syncthreads();

    // ---- mapping: 8-lane subgroup shares one pixel-QUAD ----
    // sub = og (2b) | sg (1b): lane owns o in [og*8, og*8+8), s in {sg, sg+2}
    const int  sub = tid & 7;
    const int  og  = sub & 3;
    const int  sg  = sub >> 2;
    const long quad = (long)blockIdx.x * 16 + (tid >> 3);
    const long pix0 = quad << 2;               // 16B aligned
    const int  b    = (int)(pix0 >> 17);
    const int  thw  = (int)(pix0 & (THW - 1));

    const float* fbase = feats + thw;
    const float4* fA = (const float4*)(fbase + (((long)(sg * 2 + b)) << 23));        // s = sg
    const float4* fB = (const float4*)(fbase + (((long)((sg + 2) * 2 + b)) << 23));  // s = sg+2
    const float4* pq = (const float4*)(ps + (((long)b * NP) << 17) + thw);

    // accA: s = sg, accB: s = sg+2 ; [o-local][half]  (half0 = pix0,1; half1 = pix2,3)
    u64 accA[8][2], accB[8][2];

    // ---- p-part (identical for every s: compute once) ----
#pragma unroll
    for (int i = 0; i < 8; i++) { accA[i][0] = 0ULL; accA[i][1] = 0ULL; }
#pragma unroll
    for (int p = 0; p < NP; p++) {
        float4 v = pq[(long)p << 15];
        u64 vlo = pack2(v.x, v.y), vhi = pack2(v.z, v.w);
        const u64* wr = &w1t2[64 + p][og * 8];
#pragma unroll
        for (int i = 0; i < 8; i++) {
            u64 w = wr[i];
            accA[i][0] = fma2(w, vlo, accA[i][0]);
            accA[i][1] = fma2(w, vhi, accA[i][1]);
        }
    }
#pragma unroll
    for (int i = 0; i < 8; i++) { accB[i][0] = accA[i][0]; accB[i][1] = accA[i][1]; }

    // ---- main GEMV over f ----
#pragma unroll 2
    for (int f = 0; f < NF; f++) {
        float4 a = fA[(long)f << 15];
        float4 c = fB[(long)f << 15];
        u64 alo = pack2(a.x, a.y), ahi = pack2(a.z, a.w);
        u64 clo = pack2(c.x, c.y), chi = pack2(c.z, c.w);
        const u64* wr = &w1t2[f][og * 8];
#pragma unroll
        for (int i = 0; i < 8; i++) {
            u64 w = wr[i];
            accA[i][0] = fma2(w, alo, accA[i][0]);
            accA[i][1] = fma2(w, ahi, accA[i][1]);
            accB[i][0] = fma2(w, clo, accB[i][0]);
            accB[i][1] = fma2(w, chi, accB[i][1]);
        }
    }

    // ---- BN + ReLU + w2 dot: partial logits for 4 pixels, 2 scales ----
    float lA[4] = {0, 0, 0, 0}, lB[4] = {0, 0, 0, 0};
#pragma unroll
    for (int i = 0; i < 8; i++) {
        int o = og * 8 + i;
        u64 sc = sc2[o], sh = sh2[o];
        float wv = w2s[o];
        float x, y;
        u64 h;
        h = fma2(accA[i][0], sc, sh); unpack2(h, x, y);
        lA[0] = fmaf(wv, fmaxf(x, 0.f), lA[0]); lA[1] = fmaf(wv, fmaxf(y, 0.f), lA[1]);
        h = fma2(accA[i][1], sc, sh); unpack2(h, x, y);
        lA[2] = fmaf(wv, fmaxf(x, 0.f), lA[2]); lA[3] = fmaf(wv, fmaxf(y, 0.f), lA[3]);
        h = fma2(accB[i][0], sc, sh); unpack2(h, x, y);
        lB[0] = fmaf(wv, fmaxf(x, 0.f), lB[0]); lB[1] = fmaf(wv, fmaxf(y, 0.f), lB[1]);
        h = fma2(accB[i][1], sc, sh); unpack2(h, x, y);
        lB[2] = fmaf(wv, fmaxf(x, 0.f), lB[2]); lB[3] = fmaf(wv, fmaxf(y, 0.f), lB[3]);
    }
    // o-reduce across og (lanes xor 1, 2)
#pragma unroll
    for (int k = 0; k < 4; k++) {
        lA[k] += __shfl_xor_sync(0xffffffffu, lA[k], 1);
        lA[k] += __shfl_xor_sync(0xffffffffu, lA[k], 2);
        lB[k] += __shfl_xor_sync(0xffffffffu, lB[k], 1);
        lB[k] += __shfl_xor_sync(0xffffffffu, lB[k], 2);
    }
    // s-exchange across sg (lanes xor 4): partner holds the other two scales
    float oA[4], oB[4];
#pragma unroll
    for (int k = 0; k < 4; k++) {
        oA[k] = __shfl_xor_sync(0xffffffffu, lA[k], 4);
        oB[k] = __shfl_xor_sync(0xffffffffu, lB[k], 4);
    }

    // ---- softmax over s per pixel (b2 constant -> cancels) ----
    u64 a2[4][2];   // alpha per s, packed halves
    {
        float al[4][4];   // [s][pixel]
#pragma unroll
        for (int k = 0; k < 4; k++) {
            al[sg][k]     = lA[k];
            al[sg + 2][k] = lB[k];
            al[1 - sg][k] = oA[k];
            al[3 - sg][k] = oB[k];
        }
#pragma unroll
        for (int k = 0; k < 4; k++) {
            float m = fmaxf(fmaxf(al[0][k], al[1][k]), fmaxf(al[2][k], al[3][k]));
            float e0 = __expf(al[0][k] - m);
            float e1 = __expf(al[1][k] - m);
            float e2 = __expf(al[2][k] - m);
            float e3 = __expf(al[3][k] - m);
            float r = 1.f / (e0 + e1 + e2 + e3);
            al[0][k] = e0 * r; al[1][k] = e1 * r; al[2][k] = e2 * r; al[3][k] = e3 * r;
        }
#pragma unroll
        for (int s = 0; s < 4; s++) {
            a2[s][0] = pack2(al[s][0], al[s][1]);
            a2[s][1] = pack2(al[s][2], al[s][3]);
        }
    }

    // ---- alpha output (B,S,T,H,W): one lane per quad writes ----
    if (sub == 0) {
        float4* ap = (float4*)(out + OUT_ELEMS + (((long)b * NS) << 17) + thw);
#pragma unroll
        for (int s = 0; s < 4; s++) {
            float x0, x1, x2, x3;
            unpack2(a2[s][0], x0, x1);
            unpack2(a2[s][1], x2, x3);
            ap[(long)s << 15] = make_float4(x0, x1, x2, x3);
        }
    }

    // ---- pass 2: out[f] = sum_s alpha_s * feats[s,f]; 8 lanes split 64 f ----
    const float4* fs0 = (const float4*)(fbase + (((long)(0 + b)) << 23));
    const float4* fs1 = (const float4*)(fbase + (((long)(2 + b)) << 23));
    const float4* fs2 = (const float4*)(fbase + (((long)(4 + b)) << 23));
    const float4* fs3 = (const float4*)(fbase + (((long)(6 + b)) << 23));
    float4* op = (float4*)(out + (((long)b) << 23) + thw);
#pragma unroll
    for (int j = 0; j < 8; j++) {
        const long fo = (long)(sub + 8 * j) << 15;
        float4 v0 = fs0[fo], v1 = fs1[fo], v2 = fs2[fo], v3 = fs3[fo];
        u64 rlo = mul2(a2[0][0], pack2(v0.x, v0.y));
        u64 rhi = mul2(a2[0][1], pack2(v0.z, v0.w));
        rlo = fma2(a2[1][0], pack2(v1.x, v1.y), rlo);
        rhi = fma2(a2[1][1], pack2(v1.z, v1.w), rhi);
        rlo = fma2(a2[2][0], pack2(v2.x, v2.y), rlo);
        rhi = fma2(a2[2][1], pack2(v2.z, v2.w), rhi);
        rlo = fma2(a2[3][0], pack2(v3.x, v3.y), rlo);
        rhi = fma2(a2[3][1], pack2(v3.z, v3.w), rhi);
        float x0, x1, x2, x3;
        unpack2(rlo, x0, x1);
        unpack2(rhi, x2, x3);
        op[fo] = make_float4(x0, x1, x2, x3);
    }
}

extern "C" void kernel_launch(void* const* d_in, const int* in_sizes, int n_in,
                              void* d_out, int out_size) {
    const float* feats = (const float*)d_in[0];
    const float* ps    = (const float*)d_in[1];
    const float* w1    = (const float*)d_in[2];
    const float* gamma = (const float*)d_in[3];
    const float* beta  = (const float*)d_in[4];
    const float* mean  = (const float*)d_in[5];
    const float* var   = (const float*)d_in[6];
    const float* w2    = (const float*)d_in[7];
    float* out = (float*)d_out;

    const int blocks = NPIX / 64;   // 4096: 128 threads = 16 quads = 64 pixels
    gssm_kernel<<<blocks, 128>>>(feats, ps, w1, gamma, beta, mean, var, w2, out);
}